// round 1
// baseline (speedup 1.0000x reference)
#include <cuda_runtime.h>
#include <stdint.h>

// Problem shape (fixed by the dataset)
#define NH 32
#define NL 8192
#define ND 128
#define NROWS (NH * NL)          // 262144
#define NKV   ((size_t)NROWS * ND) // 33554432

// Output layout: flattened concatenation of the reference tuple, fp32
static const size_t OFF_K   = 0;
static const size_t OFF_V   = NKV;                    // kv = stack([k,v])
static const size_t OFF_NUM = 2 * NKV;                // num_insertions (32)
static const size_t OFF_POS = OFF_NUM + NH;           // pos_new (262144)
static const size_t OFF_KQ  = OFF_POS + NROWS;        // kq_new
static const size_t OFF_KSC = OFF_KQ + NKV;           // k_scales_new
static const size_t OFF_KZ  = OFF_KSC + NROWS;        // k_zeros_new
static const size_t OFF_VQ  = OFF_KZ + NROWS;         // vq_new
static const size_t OFF_VSC = OFF_VQ + NKV;           // v_scales_new
static const size_t OFF_VZ  = OFF_VSC + NROWS;        // v_zeros_new

// Per-head argmin state: packed (orderable_float_key << 32) | slot_index.
// atomicMin gives global min score with lowest index on ties, matching jnp.argmin.
static __device__ unsigned long long g_argmin[NH];

__device__ __forceinline__ unsigned int fkey(float f) {
    unsigned int u = __float_as_uint(f);
    return (u & 0x80000000u) ? ~u : (u | 0x80000000u);
}

__global__ void init_kernel() {
    if (threadIdx.x < NH) g_argmin[threadIdx.x] = 0xFFFFFFFFFFFFFFFFull;
}

// One warp per (h,l) row. 256 threads = 8 rows per block; blocks never straddle heads
// (8192 % 8 == 0).
__global__ void __launch_bounds__(256) pass1_kernel(
    const int4*  __restrict__ kq,
    const int4*  __restrict__ vq,
    const float* __restrict__ ksc, const float* __restrict__ kz,
    const float* __restrict__ vsc, const float* __restrict__ vz,
    const int*   __restrict__ pos,
    const float* __restrict__ w,
    float* __restrict__ out)
{
    __shared__ float w_s[ND];
    const int warp = threadIdx.x >> 5;
    const int lane = threadIdx.x & 31;
    const unsigned int row = blockIdx.x * 8u + warp;
    const int h = row >> 13;            // / 8192
    const int l = row & (NL - 1);
    if (threadIdx.x < ND) w_s[threadIdx.x] = w[h * ND + threadIdx.x];
    __syncthreads();

    const size_t rbase = (size_t)row * 32 + lane;   // float4 / int4 index into row-major data

    // ================= K =================
    {
        int4 q4 = kq[rbase];
        float s = ksc[row], z = kz[row];
        // explicit mul+add (no FFMA contraction) to match unfused XLA dequant
        float x0 = __fadd_rn(__fmul_rn((float)q4.x, s), z);
        float x1 = __fadd_rn(__fmul_rn((float)q4.y, s), z);
        float x2 = __fadd_rn(__fmul_rn((float)q4.z, s), z);
        float x3 = __fadd_rn(__fmul_rn((float)q4.w, s), z);

        float mn = fminf(fminf(x0, x1), fminf(x2, x3));
        float mx = fmaxf(fmaxf(x0, x1), fmaxf(x2, x3));
        float sc = x0 * w_s[lane * 4 + 0] + x1 * w_s[lane * 4 + 1]
                 + x2 * w_s[lane * 4 + 2] + x3 * w_s[lane * 4 + 3];
        #pragma unroll
        for (int o = 16; o; o >>= 1) {
            mn = fminf(mn, __shfl_xor_sync(0xffffffffu, mn, o));
            mx = fmaxf(mx, __shfl_xor_sync(0xffffffffu, mx, o));
            sc += __shfl_xor_sync(0xffffffffu, sc, o);
        }

        ((float4*)(out + OFF_K))[rbase] = make_float4(x0, x1, x2, x3);

        // requantize: scales = max((mx-mn)/15, 1e-6); q = clip(rint((x-mn)/scales),0,15)
        float snew = fmaxf(__fdiv_rn(mx - mn, 15.0f), 1e-6f);
        float q0 = fminf(fmaxf(rintf(__fdiv_rn(x0 - mn, snew)), 0.0f), 15.0f);
        float q1 = fminf(fmaxf(rintf(__fdiv_rn(x1 - mn, snew)), 0.0f), 15.0f);
        float q2 = fminf(fmaxf(rintf(__fdiv_rn(x2 - mn, snew)), 0.0f), 15.0f);
        float q3 = fminf(fmaxf(rintf(__fdiv_rn(x3 - mn, snew)), 0.0f), 15.0f);
        ((float4*)(out + OFF_KQ))[rbase] = make_float4(q0, q1, q2, q3);

        int p = pos[row];
        if (lane == 0) {
            out[OFF_KSC + row] = snew;
            out[OFF_KZ + row]  = mn;
            out[OFF_POS + row] = (float)p;
            // eviction scoring (on pre-fill dequant K)
            float score = sc;
            if (l < 4)   score = __int_as_float(0x7F800000);   // +inf (protected)
            if (p == -1) score = __int_as_float(0xFF800000);   // -inf (empty slot)
            unsigned long long packed =
                ((unsigned long long)fkey(score) << 32) | (unsigned int)l;
            atomicMin(&g_argmin[h], packed);
        }
    }

    // ================= V =================
    {
        int4 q4 = vq[rbase];
        float s = vsc[row], z = vz[row];
        float x0 = __fadd_rn(__fmul_rn((float)q4.x, s), z);
        float x1 = __fadd_rn(__fmul_rn((float)q4.y, s), z);
        float x2 = __fadd_rn(__fmul_rn((float)q4.z, s), z);
        float x3 = __fadd_rn(__fmul_rn((float)q4.w, s), z);

        float mn = fminf(fminf(x0, x1), fminf(x2, x3));
        float mx = fmaxf(fmaxf(x0, x1), fmaxf(x2, x3));
        #pragma unroll
        for (int o = 16; o; o >>= 1) {
            mn = fminf(mn, __shfl_xor_sync(0xffffffffu, mn, o));
            mx = fmaxf(mx, __shfl_xor_sync(0xffffffffu, mx, o));
        }

        ((float4*)(out + OFF_V))[rbase] = make_float4(x0, x1, x2, x3);

        float snew = fmaxf(__fdiv_rn(mx - mn, 15.0f), 1e-6f);
        float q0 = fminf(fmaxf(rintf(__fdiv_rn(x0 - mn, snew)), 0.0f), 15.0f);
        float q1 = fminf(fmaxf(rintf(__fdiv_rn(x1 - mn, snew)), 0.0f), 15.0f);
        float q2 = fminf(fmaxf(rintf(__fdiv_rn(x2 - mn, snew)), 0.0f), 15.0f);
        float q3 = fminf(fmaxf(rintf(__fdiv_rn(x3 - mn, snew)), 0.0f), 15.0f);
        ((float4*)(out + OFF_VQ))[rbase] = make_float4(q0, q1, q2, q3);

        if (lane == 0) {
            out[OFF_VSC + row] = snew;
            out[OFF_VZ + row]  = mn;
        }
    }
}

// One warp (block of 32) per head: overwrite evicted row with new token, requantize it.
__global__ void __launch_bounds__(32) fixup_kernel(
    const float* __restrict__ k_val,
    const float* __restrict__ v_val,
    const int*   __restrict__ pos,
    const int*   __restrict__ input_pos_ptr,
    int input_pos_const,
    float* __restrict__ out)
{
    const int h = blockIdx.x;
    const int lane = threadIdx.x;
    const unsigned int idx = (unsigned int)(g_argmin[h] & 0xFFFFFFFFull);
    const unsigned int row = (unsigned int)h * NL + idx;
    const size_t rbase = (size_t)row * 32 + lane;

    const int ip = input_pos_ptr ? *input_pos_ptr : input_pos_const;
    if (lane == 0) {
        out[OFF_NUM + h]   = (pos[row] == -1) ? 1.0f : 0.0f;
        out[OFF_POS + row] = (float)ip;
    }

    // ---- K row = k_val[h] ----
    {
        float4 x = ((const float4*)k_val)[h * 32 + lane];
        float mn = fminf(fminf(x.x, x.y), fminf(x.z, x.w));
        float mx = fmaxf(fmaxf(x.x, x.y), fmaxf(x.z, x.w));
        #pragma unroll
        for (int o = 16; o; o >>= 1) {
            mn = fminf(mn, __shfl_xor_sync(0xffffffffu, mn, o));
            mx = fmaxf(mx, __shfl_xor_sync(0xffffffffu, mx, o));
        }
        ((float4*)(out + OFF_K))[rbase] = x;
        float snew = fmaxf(__fdiv_rn(mx - mn, 15.0f), 1e-6f);
        float q0 = fminf(fmaxf(rintf(__fdiv_rn(x.x - mn, snew)), 0.0f), 15.0f);
        float q1 = fminf(fmaxf(rintf(__fdiv_rn(x.y - mn, snew)), 0.0f), 15.0f);
        float q2 = fminf(fmaxf(rintf(__fdiv_rn(x.z - mn, snew)), 0.0f), 15.0f);
        float q3 = fminf(fmaxf(rintf(__fdiv_rn(x.w - mn, snew)), 0.0f), 15.0f);
        ((float4*)(out + OFF_KQ))[rbase] = make_float4(q0, q1, q2, q3);
        if (lane == 0) { out[OFF_KSC + row] = snew; out[OFF_KZ + row] = mn; }
    }

    // ---- V row = v_val[h] ----
    {
        float4 x = ((const float4*)v_val)[h * 32 + lane];
        float mn = fminf(fminf(x.x, x.y), fminf(x.z, x.w));
        float mx = fmaxf(fmaxf(x.x, x.y), fmaxf(x.z, x.w));
        #pragma unroll
        for (int o = 16; o; o >>= 1) {
            mn = fminf(mn, __shfl_xor_sync(0xffffffffu, mn, o));
            mx = fmaxf(mx, __shfl_xor_sync(0xffffffffu, mx, o));
        }
        ((float4*)(out + OFF_V))[rbase] = x;
        float snew = fmaxf(__fdiv_rn(mx - mn, 15.0f), 1e-6f);
        float q0 = fminf(fmaxf(rintf(__fdiv_rn(x.x - mn, snew)), 0.0f), 15.0f);
        float q1 = fminf(fmaxf(rintf(__fdiv_rn(x.y - mn, snew)), 0.0f), 15.0f);
        float q2 = fminf(fmaxf(rintf(__fdiv_rn(x.z - mn, snew)), 0.0f), 15.0f);
        float q3 = fminf(fmaxf(rintf(__fdiv_rn(x.w - mn, snew)), 0.0f), 15.0f);
        ((float4*)(out + OFF_VQ))[rbase] = make_float4(q0, q1, q2, q3);
        if (lane == 0) { out[OFF_VSC + row] = snew; out[OFF_VZ + row] = mn; }
    }
}

extern "C" void kernel_launch(void* const* d_in, const int* in_sizes, int n_in,
                              void* d_out, int out_size)
{
    const int4*  kq  = (const int4*)d_in[0];
    const int4*  vq  = (const int4*)d_in[1];
    const float* ksc = (const float*)d_in[2];
    const float* kz  = (const float*)d_in[3];
    const float* vsc = (const float*)d_in[4];
    const float* vz  = (const float*)d_in[5];
    const int*   pos = (const int*)d_in[6];

    const int* input_pos_ptr = nullptr;
    const float *k_val, *v_val, *w;
    if (n_in >= 11) {
        input_pos_ptr = (const int*)d_in[7];
        k_val = (const float*)d_in[8];
        v_val = (const float*)d_in[9];
        w     = (const float*)d_in[10];
    } else {
        // scalar input_pos not materialized as a buffer
        k_val = (const float*)d_in[7];
        v_val = (const float*)d_in[8];
        w     = (const float*)d_in[9];
    }
    float* out = (float*)d_out;

    init_kernel<<<1, 32>>>();
    pass1_kernel<<<NROWS / 8, 256>>>(kq, vq, ksc, kz, vsc, vz, pos, w, out);
    fixup_kernel<<<NH, 32>>>(k_val, v_val, pos, input_pos_ptr, 8192, out);
}

// round 3
// speedup vs baseline: 2.3920x; 2.3920x over previous
#include <cuda_runtime.h>
#include <stdint.h>

// Problem shape (fixed by the dataset)
#define NH 32
#define NL 8192
#define ND 128
#define NROWS (NH * NL)            // 262144
#define NKV   ((size_t)NROWS * ND) // 33554432
#define NBLK  (NROWS / 8)          // 32768 pass1 blocks, 1024 per head

// Output layout: flattened concatenation of the reference tuple, fp32
static const size_t OFF_K   = 0;
static const size_t OFF_V   = NKV;
static const size_t OFF_NUM = 2 * NKV;
static const size_t OFF_POS = OFF_NUM + NH;
static const size_t OFF_KQ  = OFF_POS + NROWS;
static const size_t OFF_KSC = OFF_KQ + NKV;
static const size_t OFF_KZ  = OFF_KSC + NROWS;
static const size_t OFF_VQ  = OFF_KZ + NROWS;
static const size_t OFF_VSC = OFF_VQ + NKV;
static const size_t OFF_VZ  = OFF_VSC + NROWS;

// Per-block argmin candidates: packed (orderable_float_key << 32) | slot_index.
// Written fresh by every pass1 replay -> no init kernel needed.
static __device__ unsigned long long g_blockmin[NBLK];

__device__ __forceinline__ unsigned int fkey(float f) {
    unsigned int u = __float_as_uint(f);
    return (u & 0x80000000u) ? ~u : (u | 0x80000000u);
}
__device__ __forceinline__ float unfkey(unsigned int k) {
    return (k & 0x80000000u) ? __uint_as_float(k & 0x7FFFFFFFu)
                             : __uint_as_float(~k);
}
__device__ __forceinline__ unsigned long long u64min(unsigned long long a,
                                                     unsigned long long b) {
    return a < b ? a : b;
}

// One warp per (h,l) row; 256 threads = 8 rows/block; 1024 blocks per head.
__global__ void __launch_bounds__(256) pass1_kernel(
    const int4*  __restrict__ kq,
    const int4*  __restrict__ vq,
    const float* __restrict__ ksc, const float* __restrict__ kz,
    const float* __restrict__ vsc, const float* __restrict__ vz,
    const int*   __restrict__ pos,
    const float* __restrict__ w,
    float* __restrict__ out)
{
    __shared__ float4 w_s[32];
    __shared__ unsigned long long blkmin[8];
    const int warp = threadIdx.x >> 5;
    const int lane = threadIdx.x & 31;
    const unsigned int row = blockIdx.x * 8u + warp;
    const int hb = blockIdx.x >> 10;      // head (constant per block)
    const int l  = row & (NL - 1);
    if (threadIdx.x < 32)
        w_s[threadIdx.x] = ((const float4*)(w + hb * ND))[threadIdx.x];
    __syncthreads();

    const size_t rbase = (size_t)row * 32 + lane;

    // ---- issue ALL loads up front (MLP) ----
    const int4 kq4 = __ldcs(&kq[rbase]);
    const int4 vq4 = __ldcs(&vq[rbase]);
    const float ks_ = ksc[row], kz_ = kz[row];
    const float vs_ = vsc[row], vz_ = vz[row];
    const int   p   = pos[row];

    // ---- dequant (explicit unfused mul+add, matches reference) ----
    float k0 = __fadd_rn(__fmul_rn((float)kq4.x, ks_), kz_);
    float k1 = __fadd_rn(__fmul_rn((float)kq4.y, ks_), kz_);
    float k2 = __fadd_rn(__fmul_rn((float)kq4.z, ks_), kz_);
    float k3 = __fadd_rn(__fmul_rn((float)kq4.w, ks_), kz_);
    float v0 = __fadd_rn(__fmul_rn((float)vq4.x, vs_), vz_);
    float v1 = __fadd_rn(__fmul_rn((float)vq4.y, vs_), vz_);
    float v2 = __fadd_rn(__fmul_rn((float)vq4.z, vs_), vz_);
    float v3 = __fadd_rn(__fmul_rn((float)vq4.w, vs_), vz_);

    // ---- warp reductions: min/max via single-instruction redux.sync on
    //      order-preserving uint keys (exact), score via shuffle butterfly ----
    unsigned int kmnU = min(min(fkey(k0), fkey(k1)), min(fkey(k2), fkey(k3)));
    unsigned int kmxU = max(max(fkey(k0), fkey(k1)), max(fkey(k2), fkey(k3)));
    unsigned int vmnU = min(min(fkey(v0), fkey(v1)), min(fkey(v2), fkey(v3)));
    unsigned int vmxU = max(max(fkey(v0), fkey(v1)), max(fkey(v2), fkey(v3)));
    kmnU = __reduce_min_sync(0xffffffffu, kmnU);
    kmxU = __reduce_max_sync(0xffffffffu, kmxU);
    vmnU = __reduce_min_sync(0xffffffffu, vmnU);
    vmxU = __reduce_max_sync(0xffffffffu, vmxU);
    const float kmn = unfkey(kmnU), kmx = unfkey(kmxU);
    const float vmn = unfkey(vmnU), vmx = unfkey(vmxU);

    const float4 wl = w_s[lane];
    float sc = k0 * wl.x + k1 * wl.y + k2 * wl.z + k3 * wl.w;
    #pragma unroll
    for (int o = 16; o; o >>= 1)
        sc += __shfl_xor_sync(0xffffffffu, sc, o);

    // ---- dequant outputs (streaming stores) ----
    __stcs((float4*)(out + OFF_K) + rbase, make_float4(k0, k1, k2, k3));
    __stcs((float4*)(out + OFF_V) + rbase, make_float4(v0, v1, v2, v3));

    // ---- requantize K ----
    {
        float snew = fmaxf(__fdiv_rn(kmx - kmn, 15.0f), 1e-6f);
        float q0 = fminf(fmaxf(rintf(__fdiv_rn(k0 - kmn, snew)), 0.0f), 15.0f);
        float q1 = fminf(fmaxf(rintf(__fdiv_rn(k1 - kmn, snew)), 0.0f), 15.0f);
        float q2 = fminf(fmaxf(rintf(__fdiv_rn(k2 - kmn, snew)), 0.0f), 15.0f);
        float q3 = fminf(fmaxf(rintf(__fdiv_rn(k3 - kmn, snew)), 0.0f), 15.0f);
        __stcs((float4*)(out + OFF_KQ) + rbase, make_float4(q0, q1, q2, q3));
        if (lane == 0) {
            out[OFF_KSC + row] = snew;
            out[OFF_KZ + row]  = kmn;
            out[OFF_POS + row] = (float)p;
        }
    }
    // ---- requantize V ----
    {
        float snew = fmaxf(__fdiv_rn(vmx - vmn, 15.0f), 1e-6f);
        float q0 = fminf(fmaxf(rintf(__fdiv_rn(v0 - vmn, snew)), 0.0f), 15.0f);
        float q1 = fminf(fmaxf(rintf(__fdiv_rn(v1 - vmn, snew)), 0.0f), 15.0f);
        float q2 = fminf(fmaxf(rintf(__fdiv_rn(v2 - vmn, snew)), 0.0f), 15.0f);
        float q3 = fminf(fmaxf(rintf(__fdiv_rn(v3 - vmn, snew)), 0.0f), 15.0f);
        __stcs((float4*)(out + OFF_VQ) + rbase, make_float4(q0, q1, q2, q3));
        if (lane == 0) {
            out[OFF_VSC + row] = snew;
            out[OFF_VZ + row]  = vmn;
        }
    }

    // ---- eviction score -> per-block min (no atomics) ----
    float score = sc;
    if (l < 4)   score = __int_as_float(0x7F800000);   // +inf (protected)
    if (p == -1) score = __int_as_float(0xFF800000);   // -inf (empty slot)
    unsigned long long packed =
        ((unsigned long long)fkey(score) << 32) | (unsigned int)l;
    if (lane == 0) blkmin[warp] = packed;
    __syncthreads();
    if (threadIdx.x == 0) {
        unsigned long long m = blkmin[0];
        #pragma unroll
        for (int i = 1; i < 8; i++) m = u64min(m, blkmin[i]);
        g_blockmin[blockIdx.x] = m;
    }
}

// One block (1024 threads) per head: reduce 1024 block-min candidates to the
// head argmin, then warp 0 overwrites the evicted row with the new token.
__global__ void __launch_bounds__(1024) fixup_kernel(
    const float* __restrict__ k_val,
    const float* __restrict__ v_val,
    const int*   __restrict__ pos,
    const int*   __restrict__ input_pos_ptr,
    int input_pos_const,
    float* __restrict__ out)
{
    __shared__ unsigned long long wmin[32];
    __shared__ unsigned int s_idx;
    const int h = blockIdx.x;
    const int t = threadIdx.x;
    const int lane = t & 31;

    unsigned long long m = g_blockmin[h * 1024 + t];
    #pragma unroll
    for (int o = 16; o; o >>= 1)
        m = u64min(m, __shfl_xor_sync(0xffffffffu, m, o));
    if (lane == 0) wmin[t >> 5] = m;
    __syncthreads();
    if (t < 32) {
        m = wmin[t];
        #pragma unroll
        for (int o = 16; o; o >>= 1)
            m = u64min(m, __shfl_xor_sync(0xffffffffu, m, o));
        if (t == 0) s_idx = (unsigned int)(m & 0xFFFFFFFFull);
    }
    __syncthreads();

    if (t >= 32) return;   // only warp 0 does the fill
    const unsigned int idx = s_idx;
    const unsigned int row = (unsigned int)h * NL + idx;
    const size_t rbase = (size_t)row * 32 + lane;

    const int ip = input_pos_ptr ? *input_pos_ptr : input_pos_const;
    if (lane == 0) {
        out[OFF_NUM + h]   = (pos[row] == -1) ? 1.0f : 0.0f;
        out[OFF_POS + row] = (float)ip;
    }

    // ---- K row = k_val[h] ----
    {
        float4 x = ((const float4*)k_val)[h * 32 + lane];
        unsigned int mnU = min(min(fkey(x.x), fkey(x.y)), min(fkey(x.z), fkey(x.w)));
        unsigned int mxU = max(max(fkey(x.x), fkey(x.y)), max(fkey(x.z), fkey(x.w)));
        mnU = __reduce_min_sync(0xffffffffu, mnU);
        mxU = __reduce_max_sync(0xffffffffu, mxU);
        float mn = unfkey(mnU), mx = unfkey(mxU);
        ((float4*)(out + OFF_K))[rbase] = x;
        float snew = fmaxf(__fdiv_rn(mx - mn, 15.0f), 1e-6f);
        float q0 = fminf(fmaxf(rintf(__fdiv_rn(x.x - mn, snew)), 0.0f), 15.0f);
        float q1 = fminf(fmaxf(rintf(__fdiv_rn(x.y - mn, snew)), 0.0f), 15.0f);
        float q2 = fminf(fmaxf(rintf(__fdiv_rn(x.z - mn, snew)), 0.0f), 15.0f);
        float q3 = fminf(fmaxf(rintf(__fdiv_rn(x.w - mn, snew)), 0.0f), 15.0f);
        ((float4*)(out + OFF_KQ))[rbase] = make_float4(q0, q1, q2, q3);
        if (lane == 0) { out[OFF_KSC + row] = snew; out[OFF_KZ + row] = mn; }
    }
    // ---- V row = v_val[h] ----
    {
        float4 x = ((const float4*)v_val)[h * 32 + lane];
        unsigned int mnU = min(min(fkey(x.x), fkey(x.y)), min(fkey(x.z), fkey(x.w)));
        unsigned int mxU = max(max(fkey(x.x), fkey(x.y)), max(fkey(x.z), fkey(x.w)));
        mnU = __reduce_min_sync(0xffffffffu, mnU);
        mxU = __reduce_max_sync(0xffffffffu, mxU);
        float mn = unfkey(mnU), mx = unfkey(mxU);
        ((float4*)(out + OFF_V))[rbase] = x;
        float snew = fmaxf(__fdiv_rn(mx - mn, 15.0f), 1e-6f);
        float q0 = fminf(fmaxf(rintf(__fdiv_rn(x.x - mn, snew)), 0.0f), 15.0f);
        float q1 = fminf(fmaxf(rintf(__fdiv_rn(x.y - mn, snew)), 0.0f), 15.0f);
        float q2 = fminf(fmaxf(rintf(__fdiv_rn(x.z - mn, snew)), 0.0f), 15.0f);
        float q3 = fminf(fmaxf(rintf(__fdiv_rn(x.w - mn, snew)), 0.0f), 15.0f);
        ((float4*)(out + OFF_VQ))[rbase] = make_float4(q0, q1, q2, q3);
        if (lane == 0) { out[OFF_VSC + row] = snew; out[OFF_VZ + row] = mn; }
    }
}

extern "C" void kernel_launch(void* const* d_in, const int* in_sizes, int n_in,
                              void* d_out, int out_size)
{
    const int4*  kq  = (const int4*)d_in[0];
    const int4*  vq  = (const int4*)d_in[1];
    const float* ksc = (const float*)d_in[2];
    const float* kz  = (const float*)d_in[3];
    const float* vsc = (const float*)d_in[4];
    const float* vz  = (const float*)d_in[5];
    const int*   pos = (const int*)d_in[6];

    const int* input_pos_ptr = nullptr;
    const float *k_val, *v_val, *w;
    if (n_in >= 11) {
        input_pos_ptr = (const int*)d_in[7];
        k_val = (const float*)d_in[8];
        v_val = (const float*)d_in[9];
        w     = (const float*)d_in[10];
    } else {
        k_val = (const float*)d_in[7];
        v_val = (const float*)d_in[8];
        w     = (const float*)d_in[9];
    }
    float* out = (float*)d_out;

    pass1_kernel<<<NBLK, 256>>>(kq, vq, ksc, kz, vsc, vz, pos, w, out);
    fixup_kernel<<<NH, 1024>>>(k_val, v_val, pos, input_pos_ptr, 8192, out);
}

// round 5
// speedup vs baseline: 2.5270x; 1.0565x over previous
#include <cuda_runtime.h>
#include <stdint.h>

// Problem shape (fixed by the dataset)
#define NH 32
#define NL 8192
#define ND 128
#define NROWS (NH * NL)            // 262144
#define NKV   ((size_t)NROWS * ND) // 33554432
#define NBLK  (NROWS / 8)          // 32768 blocks, 1024 candidates per head

// Output layout: flattened concatenation of the reference tuple, fp32
static const size_t OFF_K   = 0;
static const size_t OFF_V   = NKV;
static const size_t OFF_NUM = 2 * NKV;
static const size_t OFF_POS = OFF_NUM + NH;
static const size_t OFF_KQ  = OFF_POS + NROWS;
static const size_t OFF_KSC = OFF_KQ + NKV;
static const size_t OFF_KZ  = OFF_KSC + NROWS;
static const size_t OFF_VQ  = OFF_KZ + NROWS;
static const size_t OFF_VSC = OFF_VQ + NKV;
static const size_t OFF_VZ  = OFF_VSC + NROWS;

// Per-block argmin candidates, rewritten fully on every replay.
static __device__ unsigned long long g_blockmin[NBLK];
// Completion ticket counter; last block performs fixup and resets it to 0,
// so every graph replay starts from the same state.
static __device__ unsigned int g_ctr;

__device__ __forceinline__ unsigned int fkey(float f) {
    unsigned int u = __float_as_uint(f);
    return (u & 0x80000000u) ? ~u : (u | 0x80000000u);
}
__device__ __forceinline__ float unfkey(unsigned int k) {
    return (k & 0x80000000u) ? __uint_as_float(k & 0x7FFFFFFFu)
                             : __uint_as_float(~k);
}
__device__ __forceinline__ unsigned long long u64min(unsigned long long a,
                                                     unsigned long long b) {
    return a < b ? a : b;
}

// Fill one evicted row (K or V) with the new token and requantize it.
// One warp; `src` = k_val/v_val row (ND floats), writes deq/q/scale/zero.
__device__ __forceinline__ void fill_row(
    const float4* __restrict__ src4, float* __restrict__ out,
    size_t off_deq, size_t off_q, size_t off_sc, size_t off_z,
    unsigned int row, int lane)
{
    const size_t rbase = (size_t)row * 32 + lane;
    float4 x = src4[lane];
    unsigned int mnU = min(min(fkey(x.x), fkey(x.y)), min(fkey(x.z), fkey(x.w)));
    unsigned int mxU = max(max(fkey(x.x), fkey(x.y)), max(fkey(x.z), fkey(x.w)));
    mnU = __reduce_min_sync(0xffffffffu, mnU);
    mxU = __reduce_max_sync(0xffffffffu, mxU);
    float mn = unfkey(mnU), mx = unfkey(mxU);
    ((float4*)(out + off_deq))[rbase] = x;
    float snew = fmaxf(__fdiv_rn(mx - mn, 15.0f), 1e-6f);
    float q0 = fminf(fmaxf(rintf(__fdiv_rn(x.x - mn, snew)), 0.0f), 15.0f);
    float q1 = fminf(fmaxf(rintf(__fdiv_rn(x.y - mn, snew)), 0.0f), 15.0f);
    float q2 = fminf(fmaxf(rintf(__fdiv_rn(x.z - mn, snew)), 0.0f), 15.0f);
    float q3 = fminf(fmaxf(rintf(__fdiv_rn(x.w - mn, snew)), 0.0f), 15.0f);
    ((float4*)(out + off_q))[rbase] = make_float4(q0, q1, q2, q3);
    if (lane == 0) { out[off_sc + row] = snew; out[off_z + row] = mn; }
}

// One warp per (h,l) row; 256 threads = 8 rows/block; 1024 blocks per head.
// The last block to finish (threadfence-reduction pattern) performs the
// per-head argmin + evict/fill inline, then resets the ticket counter.
__global__ void __launch_bounds__(256) pass1_kernel(
    const int4*  __restrict__ kq,
    const int4*  __restrict__ vq,
    const float* __restrict__ ksc, const float* __restrict__ kz,
    const float* __restrict__ vsc, const float* __restrict__ vz,
    const int*   __restrict__ pos,
    const float* __restrict__ w,
    const float* __restrict__ k_val,
    const float* __restrict__ v_val,
    const int*   __restrict__ input_pos_ptr,
    int input_pos_const,
    float* __restrict__ out)
{
    __shared__ float4 w_s[32];
    __shared__ unsigned long long blkmin[8];
    __shared__ unsigned int s_ticket;
    const int warp = threadIdx.x >> 5;
    const int lane = threadIdx.x & 31;
    const unsigned int row = blockIdx.x * 8u + warp;
    const int hb = blockIdx.x >> 10;      // head (constant per block)
    const int l  = row & (NL - 1);
    if (threadIdx.x < 32)
        w_s[threadIdx.x] = ((const float4*)(w + hb * ND))[threadIdx.x];
    __syncthreads();

    const size_t rbase = (size_t)row * 32 + lane;

    // ---- issue ALL loads up front (MLP) ----
    const int4 kq4 = __ldcs(&kq[rbase]);
    const int4 vq4 = __ldcs(&vq[rbase]);
    const float ks_ = ksc[row], kz_ = kz[row];
    const float vs_ = vsc[row], vz_ = vz[row];
    const int   p   = pos[row];

    // ---- dequant (explicit unfused mul+add, matches reference) ----
    float k0 = __fadd_rn(__fmul_rn((float)kq4.x, ks_), kz_);
    float k1 = __fadd_rn(__fmul_rn((float)kq4.y, ks_), kz_);
    float k2 = __fadd_rn(__fmul_rn((float)kq4.z, ks_), kz_);
    float k3 = __fadd_rn(__fmul_rn((float)kq4.w, ks_), kz_);
    float v0 = __fadd_rn(__fmul_rn((float)vq4.x, vs_), vz_);
    float v1 = __fadd_rn(__fmul_rn((float)vq4.y, vs_), vz_);
    float v2 = __fadd_rn(__fmul_rn((float)vq4.z, vs_), vz_);
    float v3 = __fadd_rn(__fmul_rn((float)vq4.w, vs_), vz_);

    // ---- warp min/max via single-instruction redux on orderable uint keys ----
    unsigned int kmnU = min(min(fkey(k0), fkey(k1)), min(fkey(k2), fkey(k3)));
    unsigned int kmxU = max(max(fkey(k0), fkey(k1)), max(fkey(k2), fkey(k3)));
    unsigned int vmnU = min(min(fkey(v0), fkey(v1)), min(fkey(v2), fkey(v3)));
    unsigned int vmxU = max(max(fkey(v0), fkey(v1)), max(fkey(v2), fkey(v3)));
    kmnU = __reduce_min_sync(0xffffffffu, kmnU);
    kmxU = __reduce_max_sync(0xffffffffu, kmxU);
    vmnU = __reduce_min_sync(0xffffffffu, vmnU);
    vmxU = __reduce_max_sync(0xffffffffu, vmxU);
    const float kmn = unfkey(kmnU), kmx = unfkey(kmxU);
    const float vmn = unfkey(vmnU), vmx = unfkey(vmxU);

    const float4 wl = w_s[lane];
    float sc = k0 * wl.x + k1 * wl.y + k2 * wl.z + k3 * wl.w;
    #pragma unroll
    for (int o = 16; o; o >>= 1)
        sc += __shfl_xor_sync(0xffffffffu, sc, o);

    // ---- dequant outputs (streaming stores) ----
    __stcs((float4*)(out + OFF_K) + rbase, make_float4(k0, k1, k2, k3));
    __stcs((float4*)(out + OFF_V) + rbase, make_float4(v0, v1, v2, v3));

    // ---- requantize: exact div for scale + reciprocal-multiply per element.
    //      Quotients cluster at integers (requantizing quantized data), so the
    //      <=1ulp quotient perturbation cannot move rintf across a .5 boundary.
    {
        float snew = fmaxf(__fdiv_rn(kmx - kmn, 15.0f), 1e-6f);
        float inv  = __fdiv_rn(1.0f, snew);
        float q0 = fminf(fmaxf(rintf(__fmul_rn(k0 - kmn, inv)), 0.0f), 15.0f);
        float q1 = fminf(fmaxf(rintf(__fmul_rn(k1 - kmn, inv)), 0.0f), 15.0f);
        float q2 = fminf(fmaxf(rintf(__fmul_rn(k2 - kmn, inv)), 0.0f), 15.0f);
        float q3 = fminf(fmaxf(rintf(__fmul_rn(k3 - kmn, inv)), 0.0f), 15.0f);
        __stcs((float4*)(out + OFF_KQ) + rbase, make_float4(q0, q1, q2, q3));
        if (lane == 0) {
            out[OFF_KSC + row] = snew;
            out[OFF_KZ + row]  = kmn;
            out[OFF_POS + row] = (float)p;
        }
    }
    {
        float snew = fmaxf(__fdiv_rn(vmx - vmn, 15.0f), 1e-6f);
        float inv  = __fdiv_rn(1.0f, snew);
        float q0 = fminf(fmaxf(rintf(__fmul_rn(v0 - vmn, inv)), 0.0f), 15.0f);
        float q1 = fminf(fmaxf(rintf(__fmul_rn(v1 - vmn, inv)), 0.0f), 15.0f);
        float q2 = fminf(fmaxf(rintf(__fmul_rn(v2 - vmn, inv)), 0.0f), 15.0f);
        float q3 = fminf(fmaxf(rintf(__fmul_rn(v3 - vmn, inv)), 0.0f), 15.0f);
        __stcs((float4*)(out + OFF_VQ) + rbase, make_float4(q0, q1, q2, q3));
        if (lane == 0) {
            out[OFF_VSC + row] = snew;
            out[OFF_VZ + row]  = vmn;
        }
    }

    // ---- eviction score -> per-block min candidate ----
    float score = sc;
    if (l < 4)   score = __int_as_float(0x7F800000);   // +inf (protected)
    if (p == -1) score = __int_as_float(0xFF800000);   // -inf (empty slot)
    unsigned long long packed =
        ((unsigned long long)fkey(score) << 32) | (unsigned int)l;
    if (lane == 0) blkmin[warp] = packed;
    __syncthreads();
    if (threadIdx.x == 0) {
        unsigned long long m = blkmin[0];
        #pragma unroll
        for (int i = 1; i < 8; i++) m = u64min(m, blkmin[i]);
        g_blockmin[blockIdx.x] = m;
        __threadfence();                       // release: candidates + out stores
        s_ticket = atomicAdd(&g_ctr, 1u);
    }
    __syncthreads();

    // ---- last block: per-head argmin reduction + evict/fill ----
    if (s_ticket != NBLK - 1) return;
    __threadfence();                           // acquire
    if (threadIdx.x == 0) g_ctr = 0;           // reset for next graph replay

    const int ip = input_pos_ptr ? *input_pos_ptr : input_pos_const;
    // 8 warps x 4 iterations cover 32 heads; one warp per head.
    #pragma unroll
    for (int it = 0; it < 4; ++it) {
        const int h = warp + it * 8;
        const unsigned long long* base = &g_blockmin[h * 1024];
        unsigned long long m = 0xFFFFFFFFFFFFFFFFull;
        #pragma unroll
        for (int j = 0; j < 32; ++j)
            m = u64min(m, base[lane + 32 * j]);
        #pragma unroll
        for (int o = 16; o; o >>= 1)
            m = u64min(m, __shfl_xor_sync(0xffffffffu, m, o));
        const unsigned int idx = (unsigned int)(m & 0xFFFFFFFFull);
        const unsigned int erow = (unsigned int)h * NL + idx;

        if (lane == 0) {
            out[OFF_NUM + h]    = (pos[erow] == -1) ? 1.0f : 0.0f;
            out[OFF_POS + erow] = (float)ip;
        }
        fill_row((const float4*)k_val + h * 32, out,
                 OFF_K, OFF_KQ, OFF_KSC, OFF_KZ, erow, lane);
        fill_row((const float4*)v_val + h * 32, out,
                 OFF_V, OFF_VQ, OFF_VSC, OFF_VZ, erow, lane);
    }
}

extern "C" void kernel_launch(void* const* d_in, const int* in_sizes, int n_in,
                              void* d_out, int out_size)
{
    const int4*  kq  = (const int4*)d_in[0];
    const int4*  vq  = (const int4*)d_in[1];
    const float* ksc = (const float*)d_in[2];
    const float* kz  = (const float*)d_in[3];
    const float* vsc = (const float*)d_in[4];
    const float* vz  = (const float*)d_in[5];
    const int*   pos = (const int*)d_in[6];

    const int* input_pos_ptr = nullptr;
    const float *k_val, *v_val, *w;
    if (n_in >= 11) {
        input_pos_ptr = (const int*)d_in[7];
        k_val = (const float*)d_in[8];
        v_val = (const float*)d_in[9];
        w     = (const float*)d_in[10];
    } else {
        k_val = (const float*)d_in[7];
        v_val = (const float*)d_in[8];
        w     = (const float*)d_in[9];
    }
    float* out = (float*)d_out;

    pass1_kernel<<<NBLK, 256>>>(kq, vq, ksc, kz, vsc, vz, pos, w,
                                k_val, v_val, input_pos_ptr, 8192, out);
}

// round 6
// speedup vs baseline: 2.5918x; 1.0256x over previous
#include <cuda_runtime.h>
#include <stdint.h>

// Problem shape (fixed by the dataset)
#define NH 32
#define NL 8192
#define ND 128
#define NROWS (NH * NL)            // 262144
#define NKV   ((size_t)NROWS * ND) // 33554432
#define NBLK  (NROWS / 8)          // 32768 blocks, 1024 candidates per head

// Output layout: flattened concatenation of the reference tuple, fp32
static const size_t OFF_K   = 0;
static const size_t OFF_V   = NKV;
static const size_t OFF_NUM = 2 * NKV;
static const size_t OFF_POS = OFF_NUM + NH;
static const size_t OFF_KQ  = OFF_POS + NROWS;
static const size_t OFF_KSC = OFF_KQ + NKV;
static const size_t OFF_KZ  = OFF_KSC + NROWS;
static const size_t OFF_VQ  = OFF_KZ + NROWS;
static const size_t OFF_VSC = OFF_VQ + NKV;
static const size_t OFF_VZ  = OFF_VSC + NROWS;

// Per-block argmin candidates, rewritten fully on every replay.
static __device__ unsigned long long g_blockmin[NBLK];
// Completion ticket counter; last block performs fixup and resets it to 0.
static __device__ unsigned int g_ctr;

__device__ __forceinline__ unsigned int fkey(float f) {
    unsigned int u = __float_as_uint(f);
    return (u & 0x80000000u) ? ~u : (u | 0x80000000u);
}
__device__ __forceinline__ float unfkey(unsigned int k) {
    return (k & 0x80000000u) ? __uint_as_float(k & 0x7FFFFFFFu)
                             : __uint_as_float(~k);
}
__device__ __forceinline__ unsigned long long u64min(unsigned long long a,
                                                     unsigned long long b) {
    return a < b ? a : b;
}

// Fill one evicted row (K or V) with the new token and requantize it.
__device__ __forceinline__ void fill_row(
    const float4* __restrict__ src4, float* __restrict__ out,
    size_t off_deq, size_t off_q, size_t off_sc, size_t off_z,
    unsigned int row, int lane)
{
    const unsigned int rbase = row * 32u + lane;
    float4 x = src4[lane];
    float mn4 = fminf(fminf(x.x, x.y), fminf(x.z, x.w));
    float mx4 = fmaxf(fmaxf(x.x, x.y), fmaxf(x.z, x.w));
    float mn = unfkey(__reduce_min_sync(0xffffffffu, fkey(mn4)));
    float mx = unfkey(__reduce_max_sync(0xffffffffu, fkey(mx4)));
    ((float4*)(out + off_deq))[rbase] = x;
    float snew = fmaxf(__fdiv_rn(mx - mn, 15.0f), 1e-6f);
    float inv  = __fdiv_rn(1.0f, snew);
    float q0 = rintf(__fmul_rn(x.x - mn, inv));
    float q1 = rintf(__fmul_rn(x.y - mn, inv));
    float q2 = rintf(__fmul_rn(x.z - mn, inv));
    float q3 = rintf(__fmul_rn(x.w - mn, inv));
    ((float4*)(out + off_q))[rbase] = make_float4(q0, q1, q2, q3);
    if (lane == 0) { out[off_sc + row] = snew; out[off_z + row] = mn; }
}

// One warp per (h,l) row; 256 threads = 8 rows/block; 1024 blocks per head.
__global__ void __launch_bounds__(256) pass1_kernel(
    const int4*  __restrict__ kq,
    const int4*  __restrict__ vq,
    const float* __restrict__ ksc, const float* __restrict__ kz,
    const float* __restrict__ vsc, const float* __restrict__ vz,
    const int*   __restrict__ pos,
    const float* __restrict__ w,
    const float* __restrict__ k_val,
    const float* __restrict__ v_val,
    const int*   __restrict__ input_pos_ptr,
    int input_pos_const,
    float* __restrict__ out)
{
    __shared__ float4 w_s[32];
    __shared__ unsigned long long blkmin[8];
    __shared__ unsigned int s_ticket;
    const int warp = threadIdx.x >> 5;
    const int lane = threadIdx.x & 31;
    const unsigned int row = blockIdx.x * 8u + warp;
    const int hb = blockIdx.x >> 10;      // head (constant per block)
    const int l  = row & (NL - 1);
    if (threadIdx.x < 32)
        w_s[threadIdx.x] = ((const float4*)(w + hb * ND))[threadIdx.x];
    __syncthreads();

    const unsigned int rbase = row * 32u + lane;   // 32-bit stream index

    // ---- issue ALL loads up front (MLP) ----
    const int4 kq4 = __ldcs(&kq[rbase]);
    const int4 vq4 = __ldcs(&vq[rbase]);
    const float ks_ = ksc[row], kz_ = kz[row];
    const float vs_ = vsc[row], vz_ = vz[row];
    const int   p   = pos[row];

    // ---- dequant (explicit unfused mul+add, matches reference) ----
    float k0 = __fadd_rn(__fmul_rn((float)kq4.x, ks_), kz_);
    float k1 = __fadd_rn(__fmul_rn((float)kq4.y, ks_), kz_);
    float k2 = __fadd_rn(__fmul_rn((float)kq4.z, ks_), kz_);
    float k3 = __fadd_rn(__fmul_rn((float)kq4.w, ks_), kz_);
    float v0 = __fadd_rn(__fmul_rn((float)vq4.x, vs_), vz_);
    float v1 = __fadd_rn(__fmul_rn((float)vq4.y, vs_), vz_);
    float v2 = __fadd_rn(__fmul_rn((float)vq4.z, vs_), vz_);
    float v3 = __fadd_rn(__fmul_rn((float)vq4.w, vs_), vz_);

    // ---- in-thread float min/max trees, ONE key conversion per quantity,
    //      then single-instruction warp redux (bit-equivalent to before) ----
    float kmn4 = fminf(fminf(k0, k1), fminf(k2, k3));
    float kmx4 = fmaxf(fmaxf(k0, k1), fmaxf(k2, k3));
    float vmn4 = fminf(fminf(v0, v1), fminf(v2, v3));
    float vmx4 = fmaxf(fmaxf(v0, v1), fmaxf(v2, v3));
    const float kmn = unfkey(__reduce_min_sync(0xffffffffu, fkey(kmn4)));
    const float kmx = unfkey(__reduce_max_sync(0xffffffffu, fkey(kmx4)));
    const float vmn = unfkey(__reduce_min_sync(0xffffffffu, fkey(vmn4)));
    const float vmx = unfkey(__reduce_max_sync(0xffffffffu, fkey(vmx4)));

    const float4 wl = w_s[lane];
    float sc = k0 * wl.x + k1 * wl.y + k2 * wl.z + k3 * wl.w;
    #pragma unroll
    for (int o = 16; o; o >>= 1)
        sc += __shfl_xor_sync(0xffffffffu, sc, o);

    // ---- dequant outputs (streaming stores) ----
    __stcs((float4*)(out + OFF_K) + rbase, make_float4(k0, k1, k2, k3));
    __stcs((float4*)(out + OFF_V) + rbase, make_float4(v0, v1, v2, v3));

    // ---- requantize. Clamps dropped: (x-mn) >= 0 exactly and
    //      (x-mn)*inv <= 15*(1+2^-23)^2 < 15.5, so rintf lands in [0,15]. ----
    {
        float snew = fmaxf(__fdiv_rn(kmx - kmn, 15.0f), 1e-6f);
        float inv  = __fdiv_rn(1.0f, snew);
        float q0 = rintf(__fmul_rn(k0 - kmn, inv));
        float q1 = rintf(__fmul_rn(k1 - kmn, inv));
        float q2 = rintf(__fmul_rn(k2 - kmn, inv));
        float q3 = rintf(__fmul_rn(k3 - kmn, inv));
        __stcs((float4*)(out + OFF_KQ) + rbase, make_float4(q0, q1, q2, q3));
        if (lane == 0) {
            out[OFF_KSC + row] = snew;
            out[OFF_KZ + row]  = kmn;
            out[OFF_POS + row] = (float)p;
        }
    }
    {
        float snew = fmaxf(__fdiv_rn(vmx - vmn, 15.0f), 1e-6f);
        float inv  = __fdiv_rn(1.0f, snew);
        float q0 = rintf(__fmul_rn(v0 - vmn, inv));
        float q1 = rintf(__fmul_rn(v1 - vmn, inv));
        float q2 = rintf(__fmul_rn(v2 - vmn, inv));
        float q3 = rintf(__fmul_rn(v3 - vmn, inv));
        __stcs((float4*)(out + OFF_VQ) + rbase, make_float4(q0, q1, q2, q3));
        if (lane == 0) {
            out[OFF_VSC + row] = snew;
            out[OFF_VZ + row]  = vmn;
        }
    }

    // ---- eviction score -> per-block min candidate ----
    float score = sc;
    if (l < 4)   score = __int_as_float(0x7F800000);   // +inf (protected)
    if (p == -1) score = __int_as_float(0xFF800000);   // -inf (empty slot)
    unsigned long long packed =
        ((unsigned long long)fkey(score) << 32) | (unsigned int)l;
    if (lane == 0) blkmin[warp] = packed;
    __syncthreads();
    if (threadIdx.x == 0) {
        unsigned long long m = blkmin[0];
        #pragma unroll
        for (int i = 1; i < 8; i++) m = u64min(m, blkmin[i]);
        g_blockmin[blockIdx.x] = m;
        __threadfence();                       // release
        s_ticket = atomicAdd(&g_ctr, 1u);
    }
    __syncthreads();

    // ---- last block: per-head argmin reduction + evict/fill ----
    if (s_ticket != NBLK - 1) return;
    __threadfence();                           // acquire
    if (threadIdx.x == 0) g_ctr = 0;           // reset for next graph replay

    const int ip = input_pos_ptr ? *input_pos_ptr : input_pos_const;
    #pragma unroll
    for (int it = 0; it < 4; ++it) {
        const int h = warp + it * 8;
        const unsigned long long* base = &g_blockmin[h * 1024];
        unsigned long long m = 0xFFFFFFFFFFFFFFFFull;
        #pragma unroll
        for (int j = 0; j < 32; ++j)
            m = u64min(m, base[lane + 32 * j]);
        #pragma unroll
        for (int o = 16; o; o >>= 1)
            m = u64min(m, __shfl_xor_sync(0xffffffffu, m, o));
        const unsigned int idx = (unsigned int)(m & 0xFFFFFFFFull);
        const unsigned int erow = (unsigned int)h * NL + idx;

        if (lane == 0) {
            out[OFF_NUM + h]    = (pos[erow] == -1) ? 1.0f : 0.0f;
            out[OFF_POS + erow] = (float)ip;
        }
        fill_row((const float4*)k_val + h * 32, out,
                 OFF_K, OFF_KQ, OFF_KSC, OFF_KZ, erow, lane);
        fill_row((const float4*)v_val + h * 32, out,
                 OFF_V, OFF_VQ, OFF_VSC, OFF_VZ, erow, lane);
    }
}

extern "C" void kernel_launch(void* const* d_in, const int* in_sizes, int n_in,
                              void* d_out, int out_size)
{
    const int4*  kq  = (const int4*)d_in[0];
    const int4*  vq  = (const int4*)d_in[1];
    const float* ksc = (const float*)d_in[2];
    const float* kz  = (const float*)d_in[3];
    const float* vsc = (const float*)d_in[4];
    const float* vz  = (const float*)d_in[5];
    const int*   pos = (const int*)d_in[6];

    const int* input_pos_ptr = nullptr;
    const float *k_val, *v_val, *w;
    if (n_in >= 11) {
        input_pos_ptr = (const int*)d_in[7];
        k_val = (const float*)d_in[8];
        v_val = (const float*)d_in[9];
        w     = (const float*)d_in[10];
    } else {
        k_val = (const float*)d_in[7];
        v_val = (const float*)d_in[8];
        w     = (const float*)d_in[9];
    }
    float* out = (float*)d_out;

    pass1_kernel<<<NBLK, 256>>>(kq, vq, ksc, kz, vsc, vz, pos, w,
                                k_val, v_val, input_pos_ptr, 8192, out);
}

// round 13
// speedup vs baseline: 2.7170x; 1.0483x over previous
#include <cuda_runtime.h>
#include <stdint.h>

// Problem shape (fixed by the dataset)
#define NH 32
#define NL 8192
#define ND 128
#define NROWS (NH * NL)            // 262144
#define NKV   ((size_t)NROWS * ND) // 33554432
#define NBLK  (NROWS / 8)          // 32768 blocks, 1024 candidates per head

// Output layout: flattened concatenation of the reference tuple, fp32
static const size_t OFF_K   = 0;
static const size_t OFF_V   = NKV;
static const size_t OFF_NUM = 2 * NKV;
static const size_t OFF_POS = OFF_NUM + NH;
static const size_t OFF_KQ  = OFF_POS + NROWS;
static const size_t OFF_KSC = OFF_KQ + NKV;
static const size_t OFF_KZ  = OFF_KSC + NROWS;
static const size_t OFF_VQ  = OFF_KZ + NROWS;
static const size_t OFF_VSC = OFF_VQ + NKV;
static const size_t OFF_VZ  = OFF_VSC + NROWS;

// Per-block argmin candidates, rewritten fully on every replay.
static __device__ unsigned long long g_blockmin[NBLK];
// Completion ticket counter; last block performs fixup and resets it to 0.
static __device__ unsigned int g_ctr;

__device__ __forceinline__ unsigned int fkey(float f) {
    unsigned int u = __float_as_uint(f);
    return (u & 0x80000000u) ? ~u : (u | 0x80000000u);
}
__device__ __forceinline__ float unfkey(unsigned int k) {
    return (k & 0x80000000u) ? __uint_as_float(k & 0x7FFFFFFFu)
                             : __uint_as_float(~k);
}
__device__ __forceinline__ unsigned long long u64min(unsigned long long a,
                                                     unsigned long long b) {
    return a < b ? a : b;
}

// Fill one evicted row (K or V) with the new token and requantize it.
__device__ __forceinline__ void fill_row(
    const float4* __restrict__ src4, float* __restrict__ out,
    size_t off_deq, size_t off_q, size_t off_sc, size_t off_z,
    unsigned int row, int lane)
{
    const unsigned int rbase = row * 32u + lane;
    float4 x = src4[lane];
    float mn4 = fminf(fminf(x.x, x.y), fminf(x.z, x.w));
    float mx4 = fmaxf(fmaxf(x.x, x.y), fmaxf(x.z, x.w));
    float mn = unfkey(__reduce_min_sync(0xffffffffu, fkey(mn4)));
    float mx = unfkey(__reduce_max_sync(0xffffffffu, fkey(mx4)));
    ((float4*)(out + off_deq))[rbase] = x;
    float snew = fmaxf(__fdiv_rn(mx - mn, 15.0f), 1e-6f);
    float inv  = __fdividef(1.0f, snew);
    float q0 = rintf(__fmul_rn(x.x - mn, inv));
    float q1 = rintf(__fmul_rn(x.y - mn, inv));
    float q2 = rintf(__fmul_rn(x.z - mn, inv));
    float q3 = rintf(__fmul_rn(x.w - mn, inv));
    ((float4*)(out + off_q))[rbase] = make_float4(q0, q1, q2, q3);
    if (lane == 0) { out[off_sc + row] = snew; out[off_z + row] = mn; }
}

// One warp per (h,l) row; 256 threads = 8 rows/block; 1024 blocks per head.
// min-8-blocks/SM launch bound caps regs at 32 -> full occupancy.
__global__ void __launch_bounds__(256, 8) pass1_kernel(
    const int4*  __restrict__ kq,
    const int4*  __restrict__ vq,
    const float* __restrict__ ksc, const float* __restrict__ kz,
    const float* __restrict__ vsc, const float* __restrict__ vz,
    const int*   __restrict__ pos,
    const float* __restrict__ w,
    const float* __restrict__ k_val,
    const float* __restrict__ v_val,
    const int*   __restrict__ input_pos_ptr,
    int input_pos_const,
    float* __restrict__ out)
{
    __shared__ unsigned long long blkmin[8];
    __shared__ unsigned int s_ticket;
    const int warp = threadIdx.x >> 5;
    const int lane = threadIdx.x & 31;
    const unsigned int row = blockIdx.x * 8u + warp;
    const int hb = blockIdx.x >> 10;      // head (constant per block)
    const int l  = row & (NL - 1);

    const unsigned int rbase = row * 32u + lane;   // 32-bit stream index

    // ---- issue ALL loads up front (MLP); w comes from L1 (same line for
    //      every warp of the block) ----
    const int4 kq4 = __ldcs(&kq[rbase]);
    const int4 vq4 = __ldcs(&vq[rbase]);
    const float4 wl = ((const float4*)(w + hb * ND))[lane];
    const float ks_ = ksc[row], kz_ = kz[row];
    const float vs_ = vsc[row], vz_ = vz[row];
    const int   p   = pos[row];

    // ---- dequant (explicit unfused mul+add, matches reference) ----
    float k0 = __fadd_rn(__fmul_rn((float)kq4.x, ks_), kz_);
    float k1 = __fadd_rn(__fmul_rn((float)kq4.y, ks_), kz_);
    float k2 = __fadd_rn(__fmul_rn((float)kq4.z, ks_), kz_);
    float k3 = __fadd_rn(__fmul_rn((float)kq4.w, ks_), kz_);
    float v0 = __fadd_rn(__fmul_rn((float)vq4.x, vs_), vz_);
    float v1 = __fadd_rn(__fmul_rn((float)vq4.y, vs_), vz_);
    float v2 = __fadd_rn(__fmul_rn((float)vq4.z, vs_), vz_);
    float v3 = __fadd_rn(__fmul_rn((float)vq4.w, vs_), vz_);

    // ---- in-thread float min/max trees, one key conversion per quantity,
    //      then single-instruction warp redux ----
    float kmn4 = fminf(fminf(k0, k1), fminf(k2, k3));
    float kmx4 = fmaxf(fmaxf(k0, k1), fmaxf(k2, k3));
    float vmn4 = fminf(fminf(v0, v1), fminf(v2, v3));
    float vmx4 = fmaxf(fmaxf(v0, v1), fmaxf(v2, v3));
    const float kmn = unfkey(__reduce_min_sync(0xffffffffu, fkey(kmn4)));
    const float kmx = unfkey(__reduce_max_sync(0xffffffffu, fkey(kmx4)));
    const float vmn = unfkey(__reduce_min_sync(0xffffffffu, fkey(vmn4)));
    const float vmx = unfkey(__reduce_max_sync(0xffffffffu, fkey(vmx4)));

    float sc = k0 * wl.x + k1 * wl.y + k2 * wl.z + k3 * wl.w;
    #pragma unroll
    for (int o = 16; o; o >>= 1)
        sc += __shfl_xor_sync(0xffffffffu, sc, o);

    // ---- dequant outputs (streaming stores) ----
    __stcs((float4*)(out + OFF_K) + rbase, make_float4(k0, k1, k2, k3));
    __stcs((float4*)(out + OFF_V) + rbase, make_float4(v0, v1, v2, v3));

    // ---- requantize. snew stays exactly-rounded (it is an output); inv uses
    //      the fast MUFU.RCP path (<=2ulp), safe because quotients sit at
    //      integers, ~5 orders of magnitude from the .5 rounding boundary.
    //      Clamps dropped: (x-mn)>=0 exactly and (x-mn)*inv < 15.5. ----
    {
        float snew = fmaxf(__fdiv_rn(kmx - kmn, 15.0f), 1e-6f);
        float inv  = __fdividef(1.0f, snew);
        float q0 = rintf(__fmul_rn(k0 - kmn, inv));
        float q1 = rintf(__fmul_rn(k1 - kmn, inv));
        float q2 = rintf(__fmul_rn(k2 - kmn, inv));
        float q3 = rintf(__fmul_rn(k3 - kmn, inv));
        __stcs((float4*)(out + OFF_KQ) + rbase, make_float4(q0, q1, q2, q3));
        if (lane == 0) {
            out[OFF_KSC + row] = snew;
            out[OFF_KZ + row]  = kmn;
            out[OFF_POS + row] = (float)p;
        }
    }
    {
        float snew = fmaxf(__fdiv_rn(vmx - vmn, 15.0f), 1e-6f);
        float inv  = __fdividef(1.0f, snew);
        float q0 = rintf(__fmul_rn(v0 - vmn, inv));
        float q1 = rintf(__fmul_rn(v1 - vmn, inv));
        float q2 = rintf(__fmul_rn(v2 - vmn, inv));
        float q3 = rintf(__fmul_rn(v3 - vmn, inv));
        __stcs((float4*)(out + OFF_VQ) + rbase, make_float4(q0, q1, q2, q3));
        if (lane == 0) {
            out[OFF_VSC + row] = snew;
            out[OFF_VZ + row]  = vmn;
        }
    }

    // ---- eviction score -> per-block min candidate ----
    float score = sc;
    if (l < 4)   score = __int_as_float(0x7F800000);   // +inf (protected)
    if (p == -1) score = __int_as_float(0xFF800000);   // -inf (empty slot)
    unsigned long long packed =
        ((unsigned long long)fkey(score) << 32) | (unsigned int)l;
    if (lane == 0) blkmin[warp] = packed;
    __syncthreads();
    if (threadIdx.x == 0) {
        unsigned long long m = blkmin[0];
        #pragma unroll
        for (int i = 1; i < 8; i++) m = u64min(m, blkmin[i]);
        g_blockmin[blockIdx.x] = m;
        __threadfence();                       // release
        s_ticket = atomicAdd(&g_ctr, 1u);
    }
    __syncthreads();

    // ---- last block: per-head argmin reduction + evict/fill ----
    if (s_ticket != NBLK - 1) return;
    __threadfence();                           // acquire
    if (threadIdx.x == 0) g_ctr = 0;           // reset for next graph replay

    const int ip = input_pos_ptr ? *input_pos_ptr : input_pos_const;
    #pragma unroll
    for (int it = 0; it < 4; ++it) {
        const int h = warp + it * 8;
        const unsigned long long* base = &g_blockmin[h * 1024];
        unsigned long long m = 0xFFFFFFFFFFFFFFFFull;
        #pragma unroll
        for (int j = 0; j < 32; ++j)
            m = u64min(m, base[lane + 32 * j]);
        #pragma unroll
        for (int o = 16; o; o >>= 1)
            m = u64min(m, __shfl_xor_sync(0xffffffffu, m, o));
        const unsigned int idx = (unsigned int)(m & 0xFFFFFFFFull);
        const unsigned int erow = (unsigned int)h * NL + idx;

        if (lane == 0) {
            out[OFF_NUM + h]    = (pos[erow] == -1) ? 1.0f : 0.0f;
            out[OFF_POS + erow] = (float)ip;
        }
        fill_row((const float4*)k_val + h * 32, out,
                 OFF_K, OFF_KQ, OFF_KSC, OFF_KZ, erow, lane);
        fill_row((const float4*)v_val + h * 32, out,
                 OFF_V, OFF_VQ, OFF_VSC, OFF_VZ, erow, lane);
    }
}

extern "C" void kernel_launch(void* const* d_in, const int* in_sizes, int n_in,
                              void* d_out, int out_size)
{
    const int4*  kq  = (const int4*)d_in[0];
    const int4*  vq  = (const int4*)d_in[1];
    const float* ksc = (const float*)d_in[2];
    const float* kz  = (const float*)d_in[3];
    const float* vsc = (const float*)d_in[4];
    const float* vz  = (const float*)d_in[5];
    const int*   pos = (const int*)d_in[6];

    const int* input_pos_ptr = nullptr;
    const float *k_val, *v_val, *w;
    if (n_in >= 11) {
        input_pos_ptr = (const int*)d_in[7];
        k_val = (const float*)d_in[8];
        v_val = (const float*)d_in[9];
        w     = (const float*)d_in[10];
    } else {
        k_val = (const float*)d_in[7];
        v_val = (const float*)d_in[8];
        w     = (const float*)d_in[9];
    }
    float* out = (float*)d_out;

    pass1_kernel<<<NBLK, 256>>>(kq, vq, ksc, kz, vsc, vz, pos, w,
                                k_val, v_val, input_pos_ptr, 8192, out);
}